// round 12
// baseline (speedup 1.0000x reference)
#include <cuda_runtime.h>
#include <cuda_fp16.h>
#include <cstdint>

// ============================================================================
// SpikingNetwork, T=10. B=512, input=3072, hidden=2048, out=512
// 2-limb fp16 mma.sync GEMMs (w = hi + mid, residual <= 2^-22|w|) + tight
// margin flagging (1.5e-4 ~ 37 sigma of accumulation-order error) + exact
// fp32 recompute of flagged elements.
// R12: R11 GEMM skeleton (GTK=64, LDSM, 2-stage cp.async) with 3 tiles/stage;
// margin shrink kills the fixS1 issue-bound cost (~430us -> ~30us).
// ============================================================================

#define NB   512
#define NIN  3072
#define NHID 2048
#define NOUT 512
#define NT   10
#define NM   (NT * NB)     // 5120

#define MARGIN_V 1.5e-4f
#define MARGIN_O 1.5e-4f
#define CAPS 65536
#define CAPO 65536

__device__ __align__(16) __half g_Pre [NM * NIN];
__device__ __align__(16) __half g_S   [NM * NHID];
__device__ __align__(16) __half g_WinHi [NHID * NIN];
__device__ __align__(16) __half g_WinMid[NHID * NIN];
__device__ __align__(16) __half g_WoutHi [NOUT * NHID];
__device__ __align__(16) __half g_WoutMid[NOUT * NHID];
__device__ float    g_H[NM * NHID];
__device__ float    g_O[NM * NOUT];
__device__ __align__(8) uint16_t g_jmask[NB * NIN];
__device__ uint16_t g_smask[NB * NHID];
__device__ uint32_t g_k0[NT];
__device__ uint32_t g_k1[NT];
__device__ int      g_nflagS;
__device__ int      g_flagS[CAPS];
__device__ float    g_fixH[CAPS * NT];
__device__ int      g_nflagO;
__device__ int      g_flagO[CAPO];

// ---------------- threefry2x32 (JAX-exact, 20 rounds) -----------------------
__device__ __forceinline__ uint32_t rotl32(uint32_t x, int r) {
    return __funnelshift_l(x, x, r);
}
__device__ __forceinline__ void threefry2x32(uint32_t k0, uint32_t k1,
                                             uint32_t x0, uint32_t x1,
                                             uint32_t& o0, uint32_t& o1) {
    uint32_t ks2 = k0 ^ k1 ^ 0x1BD11BDAu;
    x0 += k0; x1 += k1;
#define TF_R(r) { x0 += x1; x1 = rotl32(x1, (r)); x1 ^= x0; }
    TF_R(13) TF_R(15) TF_R(26) TF_R(6)
    x0 += k1;  x1 += ks2 + 1u;
    TF_R(17) TF_R(29) TF_R(16) TF_R(24)
    x0 += ks2; x1 += k0 + 2u;
    TF_R(13) TF_R(15) TF_R(26) TF_R(6)
    x0 += k0;  x1 += k1 + 3u;
    TF_R(17) TF_R(29) TF_R(16) TF_R(24)
    x0 += k1;  x1 += ks2 + 4u;
    TF_R(13) TF_R(15) TF_R(26) TF_R(6)
    x0 += ks2; x1 += k0 + 5u;
#undef TF_R
    o0 = x0; o1 = x1;
}

// ---------------- XLA logistic ----------------------------------------------
__device__ __forceinline__ float xla_tanh_f32(float x) {
    const float kClamp = 7.90531110763549805f;
    float ax = fabsf(x);
    float xc = fminf(fmaxf(x, -kClamp), kClamp);
    float x2 = __fmul_rn(xc, xc);
    float p;
    p = __fadd_rn(__fmul_rn(x2, -2.76076847742355e-16f), 2.00018790482477e-13f);
    p = __fadd_rn(__fmul_rn(x2, p), -8.60467152213735e-11f);
    p = __fadd_rn(__fmul_rn(x2, p),  5.12229709037114e-08f);
    p = __fadd_rn(__fmul_rn(x2, p),  1.48572235717979e-05f);
    p = __fadd_rn(__fmul_rn(x2, p),  6.37261928875436e-04f);
    p = __fadd_rn(__fmul_rn(x2, p),  4.89352455891786e-03f);
    p = __fmul_rn(xc, p);
    float q;
    q = __fadd_rn(__fmul_rn(x2, 1.19825839466702e-06f), 1.18534705686654e-04f);
    q = __fadd_rn(__fmul_rn(x2, q), 2.26843463243900e-03f);
    q = __fadd_rn(__fmul_rn(x2, q), 4.89352518554385e-03f);
    float t = __fdiv_rn(p, q);
    return (ax < 0.0004f) ? x : t;
}
__device__ __forceinline__ float xla_sigmoid_f32(float x) {
    float t = xla_tanh_f32(__fmul_rn(x, 0.5f));
    return __fadd_rn(0.5f, __fmul_rn(0.5f, t));
}

// ---------------- cp.async / ldmatrix ---------------------------------------
__device__ __forceinline__ void cp16(void* dst_smem, const void* src) {
    uint32_t d = (uint32_t)__cvta_generic_to_shared(dst_smem);
    asm volatile("cp.async.cg.shared.global [%0], [%1], 16;\n" :: "r"(d), "l"(src));
}
__device__ __forceinline__ void cp_commit() { asm volatile("cp.async.commit_group;\n"); }
__device__ __forceinline__ void cp_wait1()  { asm volatile("cp.async.wait_group 1;\n"); }
__device__ __forceinline__ void cp_wait0()  { asm volatile("cp.async.wait_group 0;\n"); }

__device__ __forceinline__ void ldsm_x4(uint32_t& r0, uint32_t& r1,
                                        uint32_t& r2, uint32_t& r3, uint32_t addr) {
    asm volatile("ldmatrix.sync.aligned.m8n8.x4.shared.b16 {%0,%1,%2,%3}, [%4];"
                 : "=r"(r0), "=r"(r1), "=r"(r2), "=r"(r3) : "r"(addr));
}

// ---------------- fp16 mma m16n8k16 -----------------------------------------
__device__ __forceinline__ void mma16816(float& d0, float& d1, float& d2, float& d3,
                                         uint32_t a0, uint32_t a1, uint32_t a2, uint32_t a3,
                                         uint32_t b0, uint32_t b1) {
    asm volatile(
        "mma.sync.aligned.m16n8k16.row.col.f32.f16.f16.f32 "
        "{%0,%1,%2,%3},{%4,%5,%6,%7},{%8,%9},{%0,%1,%2,%3};"
        : "+f"(d0), "+f"(d1), "+f"(d2), "+f"(d3)
        : "r"(a0), "r"(a1), "r"(a2), "r"(a3), "r"(b0), "r"(b1));
}

// ---------------- setup (launch #1) -----------------------------------------
__global__ void k_setup() {
    int t = threadIdx.x;
    if (t == 0) { g_nflagS = 0; g_nflagO = 0; }
    if (t < NT) {
        uint32_t a, b;
        threefry2x32(0u, 42u, 0u, (uint32_t)t, a, b);
        g_k0[t] = a; g_k1[t] = b;
    }
}

// fp16 2-limb weight splits (launch #2): hi = fp16(w), mid = fp16(w - hi)
__global__ __launch_bounds__(256) void k_limbs2(const float* __restrict__ Wi,
                                                const float* __restrict__ Wo) {
    int i = blockIdx.x * blockDim.x + threadIdx.x;
    const int n1 = NHID * NIN;
    const int n2 = NOUT * NHID;
    if (i >= n1 + n2) return;
    const float* W = (i < n1) ? Wi : Wo;
    __half* Hi  = (i < n1) ? g_WinHi  : g_WoutHi;
    __half* Mid = (i < n1) ? g_WinMid : g_WoutMid;
    int k = (i < n1) ? i : i - n1;
    float w = W[k];
    __half h = __float2half_rn(w);
    float r = __fadd_rn(w, -__half2float(h));
    Hi[k] = h;
    Mid[k] = __float2half_rn(r);
}

// ---------------- K1: stochastic input spikes (launch #3) -------------------
__global__ __launch_bounds__(256) void k_gen(const float* __restrict__ x) {
    int idx = blockIdx.x * blockDim.x + threadIdx.x;
    if (idx >= NB * NIN) return;
    int b = idx / NIN, j = idx - b * NIN;
    float p = xla_sigmoid_f32(x[idx]);
    uint32_t m = 0;
#pragma unroll
    for (int t = 0; t < NT; t++) {
        uint32_t a, bb;
        threefry2x32(g_k0[t], g_k1[t], 0u, (uint32_t)idx, a, bb);
        uint32_t bits = a ^ bb;
        float u = __uint_as_float((bits >> 9) | 0x3F800000u) - 1.0f;
        m |= (u < p) ? (1u << t) : 0u;
    }
    g_jmask[idx] = (uint16_t)m;
    const __half one = __float2half(1.0f);
    const __half zero = __float2half(0.0f);
#pragma unroll
    for (int t = 0; t < NT; t++)
        g_Pre[(size_t)(t * NB + b) * NIN + j] = ((m >> t) & 1u) ? one : zero;
}

// ---------------- fp16 2-limb tensor-core GEMM (launch #4) ------------------
// C[m][n] = sum_k A[m][k]*(BH[n][k]+BM[n][k]); CTA 128x128x64, 8 warps,
// warp 64x32, m16n8k16, 2-stage cp.async pipeline, LDSM fragments.
#define GTK 64
#define ROWH 72                             // halves per smem row (144B stride)
#define NSTG 2
#define TILE_ELN (128 * ROWH)               // 9216 halves
#define STAGE_ELN (3 * TILE_ELN)            // A + BH + BM per stage
#define SMEM_BYTES (NSTG * STAGE_ELN * 2)   // 110592

__global__ __launch_bounds__(256)
void gemm_mma(const __half* __restrict__ A,
              const __half* __restrict__ BH,
              const __half* __restrict__ BM,
              float* __restrict__ C, int M, int N, int K) {
    extern __shared__ __half smem[];

    const int tid  = threadIdx.x;
    const int m0   = blockIdx.y * 128;
    const int n0   = blockIdx.x * 128;
    const int warp = tid >> 5;
    const int lane = tid & 31;
    const int wm   = (warp & 1) * 64;
    const int wn   = (warp >> 1) * 32;
    const int r    = lane >> 2;
    const int c2   = (lane & 3) * 2;

    const uint32_t sbase = (uint32_t)__cvta_generic_to_shared(smem);
    const uint32_t aLane = (uint32_t)(((wm + (lane & 15)) * ROWH + ((lane >> 4) * 8)) * 2);
    const uint32_t bLane = (uint32_t)(((wn + 8 * (lane >> 4) + (lane & 7)) * ROWH
                                       + (((lane >> 3) & 1) * 8)) * 2);

    float acc[4][4][4];
#pragma unroll
    for (int mi = 0; mi < 4; mi++)
#pragma unroll
        for (int nj = 0; nj < 4; nj++)
#pragma unroll
            for (int q = 0; q < 4; q++) acc[mi][nj][q] = 0.0f;

    auto issue_slab = [&](int kb, int s) {
        __half* st = smem + s * STAGE_ELN;
#pragma unroll
        for (int it = 0; it < 4; it++) {
            int idx = it * 256 + tid;       // 0..1023
            int row = idx >> 3;
            int ch  = idx & 7;
            size_t go = (size_t)row * K + kb + ch * 8;
            int so = row * ROWH + ch * 8;
            cp16(st + so,                A  + (size_t)m0 * K + go);
            cp16(st + TILE_ELN + so,     BH + (size_t)n0 * K + go);
            cp16(st + 2 * TILE_ELN + so, BM + (size_t)n0 * K + go);
        }
        cp_commit();
    };

    const int nslab = K / GTK;
    issue_slab(0, 0);
    int s = 0;
    for (int sl = 0; sl < nslab; sl++) {
        if (sl + 1 < nslab) { issue_slab((sl + 1) * GTK, s ^ 1); cp_wait1(); }
        else                { cp_wait0(); }
        __syncthreads();

        const uint32_t stA  = sbase + (uint32_t)(s * STAGE_ELN) * 2;
        const uint32_t stBH = stA + TILE_ELN * 2;
        const uint32_t stBM = stBH + TILE_ELN * 2;

#pragma unroll
        for (int kc = 0; kc < 4; kc++) {    // four k16 steps in the 64-k slab
            const uint32_t kh2 = (uint32_t)(kc * 16 * 2);
            uint32_t af[4][4];
#pragma unroll
            for (int mi = 0; mi < 4; mi++)
                ldsm_x4(af[mi][0], af[mi][1], af[mi][2], af[mi][3],
                        stA + aLane + (uint32_t)(16 * mi * ROWH * 2) + kh2);

            uint32_t bf[4][2];
#pragma unroll
            for (int p = 0; p < 2; p++) {
                uint32_t r0, r1, r2, r3;
                ldsm_x4(r0, r1, r2, r3,
                        stBH + bLane + (uint32_t)(16 * p * ROWH * 2) + kh2);
                bf[2 * p][0] = r0; bf[2 * p][1] = r1;
                bf[2 * p + 1][0] = r2; bf[2 * p + 1][1] = r3;
            }
#pragma unroll
            for (int mi = 0; mi < 4; mi++)
#pragma unroll
                for (int nj = 0; nj < 4; nj++)
                    mma16816(acc[mi][nj][0], acc[mi][nj][1], acc[mi][nj][2], acc[mi][nj][3],
                             af[mi][0], af[mi][1], af[mi][2], af[mi][3],
                             bf[nj][0], bf[nj][1]);

#pragma unroll
            for (int p = 0; p < 2; p++) {
                uint32_t r0, r1, r2, r3;
                ldsm_x4(r0, r1, r2, r3,
                        stBM + bLane + (uint32_t)(16 * p * ROWH * 2) + kh2);
                bf[2 * p][0] = r0; bf[2 * p][1] = r1;
                bf[2 * p + 1][0] = r2; bf[2 * p + 1][1] = r3;
            }
#pragma unroll
            for (int mi = 0; mi < 4; mi++)
#pragma unroll
                for (int nj = 0; nj < 4; nj++)
                    mma16816(acc[mi][nj][0], acc[mi][nj][1], acc[mi][nj][2], acc[mi][nj][3],
                             af[mi][0], af[mi][1], af[mi][2], af[mi][3],
                             bf[nj][0], bf[nj][1]);
        }
        __syncthreads();
        s ^= 1;
    }

#pragma unroll
    for (int mi = 0; mi < 4; mi++)
#pragma unroll
        for (int nj = 0; nj < 4; nj++) {
            int row = m0 + wm + 16 * mi + r;
            int col = n0 + wn + 8 * nj + c2;
            *(float2*)&C[(size_t)row * N + col] =
                make_float2(acc[mi][nj][0], acc[mi][nj][1]);
            *(float2*)&C[(size_t)(row + 8) * N + col] =
                make_float2(acc[mi][nj][2], acc[mi][nj][3]);
        }
}

// ---------------- K3: LIF scan + flagging -----------------------------------
__global__ __launch_bounds__(256) void k_lif() {
    int i = blockIdx.x * blockDim.x + threadIdx.x;
    if (i >= NB * NHID) return;
    int b = i >> 11, h = i & (NHID - 1);
    float v = 0.0f;
    uint32_t m = 0;
    bool flag = false;
#pragma unroll
    for (int t = 0; t < NT; t++) {
        float hv = g_H[(size_t)(t * NB + b) * NHID + h];
        v = __fadd_rn(__fmul_rn(v, 0.3f), hv);
        flag |= fabsf(v - 1.0f) < MARGIN_V;
        if (v >= 1.0f) { m |= (1u << t); v = 0.0f; }
    }
    g_smask[i] = (uint16_t)m;
    const __half one = __float2half(1.0f);
    const __half zero = __float2half(0.0f);
#pragma unroll
    for (int t = 0; t < NT; t++)
        g_S[(size_t)(t * NB + b) * NHID + h] = ((m >> t) & 1u) ? one : zero;
    if (flag) {
        int pos = atomicAdd(&g_nflagS, 1);
        if (pos < CAPS) g_flagS[pos] = i;
    }
}

// exact h for flagged pairs: one thread per (pair, t); vectorized loads,
// strict ascending-j fp32 chain (zero-skip is bit-exact).
__global__ __launch_bounds__(256) void k_fixS1(const float* __restrict__ W_in) {
    int idx = blockIdx.x * blockDim.x + threadIdx.x;
    int n = g_nflagS; if (n > CAPS) n = CAPS;
    int pr = idx / NT, t = idx - pr * NT;
    if (pr >= n) return;
    int i = g_flagS[pr];
    int b = i >> 11, h = i & (NHID - 1);
    const uint16_t* mrow = g_jmask + (size_t)b * NIN;
    const float* wrow = W_in + (size_t)h * NIN;
    float acc = 0.0f;
    for (int j = 0; j < NIN; j += 4) {
        float4 w = *(const float4*)(wrow + j);
        uint64_t mk = *(const uint64_t*)(mrow + j);
        if ((mk >> t) & 1u)        acc = __fadd_rn(acc, w.x);
        if ((mk >> (16 + t)) & 1u) acc = __fadd_rn(acc, w.y);
        if ((mk >> (32 + t)) & 1u) acc = __fadd_rn(acc, w.z);
        if ((mk >> (48 + t)) & 1u) acc = __fadd_rn(acc, w.w);
    }
    g_fixH[pr * NT + t] = acc;
}

// exact v-chain + spike rewrite for flagged pairs
__global__ __launch_bounds__(256) void k_fixS2() {
    int idx = blockIdx.x * blockDim.x + threadIdx.x;
    int n = g_nflagS; if (n > CAPS) n = CAPS;
    if (idx >= n) return;
    int i = g_flagS[idx];
    int b = i >> 11, h = i & (NHID - 1);
    float v = 0.0f;
    uint32_t m = 0;
#pragma unroll
    for (int t = 0; t < NT; t++) {
        v = __fadd_rn(__fmul_rn(v, 0.3f), g_fixH[idx * NT + t]);
        if (v >= 1.0f) { m |= (1u << t); v = 0.0f; }
    }
    g_smask[i] = (uint16_t)m;
    const __half one = __float2half(1.0f);
    const __half zero = __float2half(0.0f);
#pragma unroll
    for (int t = 0; t < NT; t++)
        g_S[(size_t)(t * NB + b) * NHID + h] = ((m >> t) & 1u) ? one : zero;
}

// ---------------- output flag + exact fix + count ---------------------------
__global__ __launch_bounds__(256) void k_flagO(const float* __restrict__ b_out) {
    int i = blockIdx.x * blockDim.x + threadIdx.x;
    if (i >= NM * NOUT) return;
    float val = __fadd_rn(g_O[i], b_out[i & (NOUT - 1)]);
    if (fabsf(val) < MARGIN_O) {
        int pos = atomicAdd(&g_nflagO, 1);
        if (pos < CAPO) g_flagO[pos] = i;
    }
}

__global__ __launch_bounds__(256) void k_fixO(const float* __restrict__ W_out) {
    int idx = blockIdx.x * blockDim.x + threadIdx.x;
    int n = g_nflagO; if (n > CAPO) n = CAPO;
    if (idx >= n) return;
    int i = g_flagO[idx];
    int m = i / NOUT, o = i - m * NOUT;
    int b = m & (NB - 1), t = m / NB;
    const uint16_t* srow = g_smask + (size_t)b * NHID;
    const float* wrow = W_out + (size_t)o * NHID;
    float acc = 0.0f;
    for (int h = 0; h < NHID; h++) {
        float w = wrow[h];
        acc = __fadd_rn(acc, ((srow[h] >> t) & 1u) ? w : 0.0f);
    }
    g_O[i] = acc;
}

__global__ __launch_bounds__(256) void k_count(const float* __restrict__ b_out,
                                               float* __restrict__ out) {
    int i = blockIdx.x * blockDim.x + threadIdx.x;
    if (i >= NB * NOUT) return;
    float bo = b_out[i & (NOUT - 1)];
    float s = 0.0f;
#pragma unroll
    for (int t = 0; t < NT; t++) {
        float val = __fadd_rn(g_O[(size_t)t * (NB * NOUT) + i], bo);
        s += (val > 0.0f) ? 1.0f : 0.0f;
    }
    out[i] = s;
}

// ---------------- launch ----------------------------------------------------
extern "C" void kernel_launch(void* const* d_in, const int* in_sizes, int n_in,
                              void* d_out, int out_size) {
    const float* x     = (const float*)d_in[0];
    const float* W_in  = (const float*)d_in[1];
    const float* W_out = (const float*)d_in[2];
    const float* b_out = (const float*)d_in[3];
    float* out = (float*)d_out;

    static bool attr_set = false;
    if (!attr_set) {
        cudaFuncSetAttribute(gemm_mma, cudaFuncAttributeMaxDynamicSharedMemorySize,
                             SMEM_BYTES);
        attr_set = true;
    }

    void *p_Pre, *p_S, *p_WiH, *p_WiM, *p_WoH, *p_WoM, *p_H, *p_O;
    cudaGetSymbolAddress(&p_Pre, g_Pre);
    cudaGetSymbolAddress(&p_S,   g_S);
    cudaGetSymbolAddress(&p_WiH, g_WinHi);
    cudaGetSymbolAddress(&p_WiM, g_WinMid);
    cudaGetSymbolAddress(&p_WoH, g_WoutHi);
    cudaGetSymbolAddress(&p_WoM, g_WoutMid);
    cudaGetSymbolAddress(&p_H,   g_H);
    cudaGetSymbolAddress(&p_O,   g_O);

    k_setup<<<1, 32>>>();                                            // #1
    k_limbs2<<<(NHID * NIN + NOUT * NHID + 255) / 256, 256>>>(W_in, W_out); // #2
    k_gen<<<(NB * NIN + 255) / 256, 256>>>(x);                       // #3

    {   // #4 (ncu-captured): H = PRE @ W_in^T
        dim3 grid(NHID / 128, NM / 128);
        gemm_mma<<<grid, 256, SMEM_BYTES>>>((const __half*)p_Pre,
            (const __half*)p_WiH, (const __half*)p_WiM,
            (float*)p_H, NM, NHID, NIN);
    }

    k_lif<<<(NB * NHID + 255) / 256, 256>>>();                       // #5
    k_fixS1<<<(CAPS * NT + 255) / 256, 256>>>(W_in);                 // #6
    k_fixS2<<<(CAPS + 255) / 256, 256>>>();                          // #7

    {   // #8: O = S @ W_out^T
        dim3 grid(NOUT / 128, NM / 128);
        gemm_mma<<<grid, 256, SMEM_BYTES>>>((const __half*)p_S,
            (const __half*)p_WoH, (const __half*)p_WoM,
            (float*)p_O, NM, NOUT, NHID);
    }

    k_flagO<<<(NM * NOUT + 255) / 256, 256>>>(b_out);                // #9
    k_fixO<<<(CAPO + 255) / 256, 256>>>(W_out);                      // #10
    k_count<<<(NB * NOUT + 255) / 256, 256>>>(b_out, out);           // #11
}

// round 13
// speedup vs baseline: 1.2195x; 1.2195x over previous
#include <cuda_runtime.h>
#include <cuda_fp16.h>
#include <cstdint>

// ============================================================================
// SpikingNetwork, T=10. B=512, input=3072, hidden=2048, out=512
// R13 = R11 (best, 1087us) with setup+half2+gen merged into one k_prep kernel:
// fewer launches AND shifts ncu capture (#4) onto k_fixS1 — the largest
// unmeasured cost center. GEMM/margins/fixups identical to R11.
// ============================================================================

#define NB   512
#define NIN  3072
#define NHID 2048
#define NOUT 512
#define NT   10
#define NM   (NT * NB)     // 5120

#define MARGIN_V 2.0e-3f
#define MARGIN_O 1.5e-3f
#define CAPS 131072
#define CAPO 131072

__device__ __align__(16) __half g_Pre [NM * NIN];
__device__ __align__(16) __half g_S   [NM * NHID];
__device__ __align__(16) __half g_WinH [NHID * NIN];
__device__ __align__(16) __half g_WoutH[NOUT * NHID];
__device__ float    g_H[NM * NHID];
__device__ float    g_O[NM * NOUT];
__device__ __align__(8) uint16_t g_jmask[NB * NIN];
__device__ uint16_t g_smask[NB * NHID];
__device__ int      g_nflagS;
__device__ int      g_flagS[CAPS];
__device__ float    g_fixH[CAPS * NT];
__device__ int      g_nflagO;
__device__ int      g_flagO[CAPO];

// ---------------- threefry2x32 (JAX-exact, 20 rounds) -----------------------
__device__ __forceinline__ uint32_t rotl32(uint32_t x, int r) {
    return __funnelshift_l(x, x, r);
}
__device__ __forceinline__ void threefry2x32(uint32_t k0, uint32_t k1,
                                             uint32_t x0, uint32_t x1,
                                             uint32_t& o0, uint32_t& o1) {
    uint32_t ks2 = k0 ^ k1 ^ 0x1BD11BDAu;
    x0 += k0; x1 += k1;
#define TF_R(r) { x0 += x1; x1 = rotl32(x1, (r)); x1 ^= x0; }
    TF_R(13) TF_R(15) TF_R(26) TF_R(6)
    x0 += k1;  x1 += ks2 + 1u;
    TF_R(17) TF_R(29) TF_R(16) TF_R(24)
    x0 += ks2; x1 += k0 + 2u;
    TF_R(13) TF_R(15) TF_R(26) TF_R(6)
    x0 += k0;  x1 += k1 + 3u;
    TF_R(17) TF_R(29) TF_R(16) TF_R(24)
    x0 += k1;  x1 += ks2 + 4u;
    TF_R(13) TF_R(15) TF_R(26) TF_R(6)
    x0 += ks2; x1 += k0 + 5u;
#undef TF_R
    o0 = x0; o1 = x1;
}

// ---------------- XLA logistic ----------------------------------------------
__device__ __forceinline__ float xla_tanh_f32(float x) {
    const float kClamp = 7.90531110763549805f;
    float ax = fabsf(x);
    float xc = fminf(fmaxf(x, -kClamp), kClamp);
    float x2 = __fmul_rn(xc, xc);
    float p;
    p = __fadd_rn(__fmul_rn(x2, -2.76076847742355e-16f), 2.00018790482477e-13f);
    p = __fadd_rn(__fmul_rn(x2, p), -8.60467152213735e-11f);
    p = __fadd_rn(__fmul_rn(x2, p),  5.12229709037114e-08f);
    p = __fadd_rn(__fmul_rn(x2, p),  1.48572235717979e-05f);
    p = __fadd_rn(__fmul_rn(x2, p),  6.37261928875436e-04f);
    p = __fadd_rn(__fmul_rn(x2, p),  4.89352455891786e-03f);
    p = __fmul_rn(xc, p);
    float q;
    q = __fadd_rn(__fmul_rn(x2, 1.19825839466702e-06f), 1.18534705686654e-04f);
    q = __fadd_rn(__fmul_rn(x2, q), 2.26843463243900e-03f);
    q = __fadd_rn(__fmul_rn(x2, q), 4.89352518554385e-03f);
    float t = __fdiv_rn(p, q);
    return (ax < 0.0004f) ? x : t;
}
__device__ __forceinline__ float xla_sigmoid_f32(float x) {
    float t = xla_tanh_f32(__fmul_rn(x, 0.5f));
    return __fadd_rn(0.5f, __fmul_rn(0.5f, t));
}

// ---------------- cp.async / ldmatrix ---------------------------------------
__device__ __forceinline__ void cp16(void* dst_smem, const void* src) {
    uint32_t d = (uint32_t)__cvta_generic_to_shared(dst_smem);
    asm volatile("cp.async.cg.shared.global [%0], [%1], 16;\n" :: "r"(d), "l"(src));
}
__device__ __forceinline__ void cp_commit() { asm volatile("cp.async.commit_group;\n"); }
__device__ __forceinline__ void cp_wait1()  { asm volatile("cp.async.wait_group 1;\n"); }
__device__ __forceinline__ void cp_wait0()  { asm volatile("cp.async.wait_group 0;\n"); }

__device__ __forceinline__ void ldsm_x4(uint32_t& r0, uint32_t& r1,
                                        uint32_t& r2, uint32_t& r3, uint32_t addr) {
    asm volatile("ldmatrix.sync.aligned.m8n8.x4.shared.b16 {%0,%1,%2,%3}, [%4];"
                 : "=r"(r0), "=r"(r1), "=r"(r2), "=r"(r3) : "r"(addr));
}

// ---------------- fp16 mma m16n8k16 -----------------------------------------
__device__ __forceinline__ void mma16816(float& d0, float& d1, float& d2, float& d3,
                                         uint32_t a0, uint32_t a1, uint32_t a2, uint32_t a3,
                                         uint32_t b0, uint32_t b1) {
    asm volatile(
        "mma.sync.aligned.m16n8k16.row.col.f32.f16.f16.f32 "
        "{%0,%1,%2,%3},{%4,%5,%6,%7},{%8,%9},{%0,%1,%2,%3};"
        : "+f"(d0), "+f"(d1), "+f"(d2), "+f"(d3)
        : "r"(a0), "r"(a1), "r"(a2), "r"(a3), "r"(b0), "r"(b1));
}

// ---------------- K_prep (launch #1): setup + weight casts + spike gen ------
// Blocks [0, PREP_W_BLOCKS): fp16 weight casts (+ block 0 zeroes counters).
// Blocks [PREP_W_BLOCKS, ...): stochastic input spikes; per-block threefry
// keys recomputed into smem (identical values to the old k_setup).
#define PREP_W_ELN   (NHID * NIN + NOUT * NHID)       // 7340032
#define PREP_W_BLOCKS (PREP_W_ELN / 256)              // 28672
#define PREP_G_BLOCKS ((NB * NIN) / 256)              // 6144

__global__ __launch_bounds__(256) void k_prep(const float* __restrict__ x,
                                              const float* __restrict__ Wi,
                                              const float* __restrict__ Wo) {
    const int blk = blockIdx.x;
    if (blk < PREP_W_BLOCKS) {
        if (blk == 0 && threadIdx.x == 0) { g_nflagS = 0; g_nflagO = 0; }
        int i = blk * 256 + threadIdx.x;
        const int n1 = NHID * NIN;
        if (i < n1) g_WinH[i] = __float2half_rn(Wi[i]);
        else        g_WoutH[i - n1] = __float2half_rn(Wo[i - n1]);
        return;
    }
    __shared__ uint32_t sk0[NT], sk1[NT];
    if (threadIdx.x < NT) {
        uint32_t a, b;
        threefry2x32(0u, 42u, 0u, (uint32_t)threadIdx.x, a, b);
        sk0[threadIdx.x] = a; sk1[threadIdx.x] = b;
    }
    __syncthreads();
    int idx = (blk - PREP_W_BLOCKS) * 256 + threadIdx.x;
    int b = idx / NIN, j = idx - b * NIN;
    float p = xla_sigmoid_f32(x[idx]);
    uint32_t m = 0;
#pragma unroll
    for (int t = 0; t < NT; t++) {
        uint32_t a, bb;
        threefry2x32(sk0[t], sk1[t], 0u, (uint32_t)idx, a, bb);
        uint32_t bits = a ^ bb;
        float u = __uint_as_float((bits >> 9) | 0x3F800000u) - 1.0f;
        m |= (u < p) ? (1u << t) : 0u;
    }
    g_jmask[idx] = (uint16_t)m;
    const __half one = __float2half(1.0f);
    const __half zero = __float2half(0.0f);
#pragma unroll
    for (int t = 0; t < NT; t++)
        g_Pre[(size_t)(t * NB + b) * NIN + j] = ((m >> t) & 1u) ? one : zero;
}

// ---------------- fp16 tensor-core GEMM (launch #2) -------------------------
// C[m][n] = sum_k A[m][k]*B[n][k]; CTA 128x128x64, 8 warps, warp 64x32,
// m16n8k16, 2-stage cp.async pipeline, ldmatrix.x4 fragment loads.
#define GTK 64
#define ROWH 72
#define NSTG 2
#define TILE_ELN (128 * ROWH)
#define STAGE_ELN (2 * TILE_ELN)
#define SMEM_BYTES (NSTG * STAGE_ELN * 2)   // 73728

__global__ __launch_bounds__(256)
void gemm_mma(const __half* __restrict__ A,
              const __half* __restrict__ B,
              float* __restrict__ C, int M, int N, int K) {
    extern __shared__ __half smem[];

    const int tid  = threadIdx.x;
    const int m0   = blockIdx.y * 128;
    const int n0   = blockIdx.x * 128;
    const int warp = tid >> 5;
    const int lane = tid & 31;
    const int wm   = (warp & 1) * 64;
    const int wn   = (warp >> 1) * 32;
    const int r    = lane >> 2;
    const int c2   = (lane & 3) * 2;

    const uint32_t sbase = (uint32_t)__cvta_generic_to_shared(smem);
    const uint32_t aLane = (uint32_t)(((wm + (lane & 15)) * ROWH + ((lane >> 4) * 8)) * 2);
    const uint32_t bLane = (uint32_t)(((wn + 8 * (lane >> 4) + (lane & 7)) * ROWH
                                       + (((lane >> 3) & 1) * 8)) * 2);

    float acc[4][4][4];
#pragma unroll
    for (int mi = 0; mi < 4; mi++)
#pragma unroll
        for (int nj = 0; nj < 4; nj++)
#pragma unroll
            for (int q = 0; q < 4; q++) acc[mi][nj][q] = 0.0f;

    auto issue_slab = [&](int kb, int s) {
        __half* st = smem + s * STAGE_ELN;
#pragma unroll
        for (int it = 0; it < 4; it++) {
            int idx = it * 256 + tid;
            int row = idx >> 3;
            int ch  = idx & 7;
            size_t go = (size_t)row * K + kb + ch * 8;
            int so = row * ROWH + ch * 8;
            cp16(st + so,            A + (size_t)m0 * K + go);
            cp16(st + TILE_ELN + so, B + (size_t)n0 * K + go);
        }
        cp_commit();
    };

    const int nslab = K / GTK;
    issue_slab(0, 0);
    int s = 0;
    for (int sl = 0; sl < nslab; sl++) {
        if (sl + 1 < nslab) { issue_slab((sl + 1) * GTK, s ^ 1); cp_wait1(); }
        else                { cp_wait0(); }
        __syncthreads();

        const uint32_t stA = sbase + (uint32_t)(s * STAGE_ELN) * 2;
        const uint32_t stB = stA + TILE_ELN * 2;

#pragma unroll
        for (int kc = 0; kc < 4; kc++) {
            const uint32_t kh2 = (uint32_t)(kc * 16 * 2);
            uint32_t af[4][4];
#pragma unroll
            for (int mi = 0; mi < 4; mi++)
                ldsm_x4(af[mi][0], af[mi][1], af[mi][2], af[mi][3],
                        stA + aLane + (uint32_t)(16 * mi * ROWH * 2) + kh2);

            uint32_t bf[4][2];
#pragma unroll
            for (int p = 0; p < 2; p++) {
                uint32_t r0, r1, r2, r3;
                ldsm_x4(r0, r1, r2, r3,
                        stB + bLane + (uint32_t)(16 * p * ROWH * 2) + kh2);
                bf[2 * p][0] = r0; bf[2 * p][1] = r1;
                bf[2 * p + 1][0] = r2; bf[2 * p + 1][1] = r3;
            }
#pragma unroll
            for (int mi = 0; mi < 4; mi++)
#pragma unroll
                for (int nj = 0; nj < 4; nj++)
                    mma16816(acc[mi][nj][0], acc[mi][nj][1], acc[mi][nj][2], acc[mi][nj][3],
                             af[mi][0], af[mi][1], af[mi][2], af[mi][3],
                             bf[nj][0], bf[nj][1]);
        }
        __syncthreads();
        s ^= 1;
    }

#pragma unroll
    for (int mi = 0; mi < 4; mi++)
#pragma unroll
        for (int nj = 0; nj < 4; nj++) {
            int row = m0 + wm + 16 * mi + r;
            int col = n0 + wn + 8 * nj + c2;
            *(float2*)&C[(size_t)row * N + col] =
                make_float2(acc[mi][nj][0], acc[mi][nj][1]);
            *(float2*)&C[(size_t)(row + 8) * N + col] =
                make_float2(acc[mi][nj][2], acc[mi][nj][3]);
        }
}

// ---------------- K_lif (launch #3): LIF scan + flagging --------------------
__global__ __launch_bounds__(256) void k_lif() {
    int i = blockIdx.x * blockDim.x + threadIdx.x;
    if (i >= NB * NHID) return;
    int b = i >> 11, h = i & (NHID - 1);
    float v = 0.0f;
    uint32_t m = 0;
    bool flag = false;
#pragma unroll
    for (int t = 0; t < NT; t++) {
        float hv = g_H[(size_t)(t * NB + b) * NHID + h];
        v = __fadd_rn(__fmul_rn(v, 0.3f), hv);
        flag |= fabsf(v - 1.0f) < MARGIN_V;
        if (v >= 1.0f) { m |= (1u << t); v = 0.0f; }
    }
    g_smask[i] = (uint16_t)m;
    const __half one = __float2half(1.0f);
    const __half zero = __float2half(0.0f);
#pragma unroll
    for (int t = 0; t < NT; t++)
        g_S[(size_t)(t * NB + b) * NHID + h] = ((m >> t) & 1u) ? one : zero;
    if (flag) {
        int pos = atomicAdd(&g_nflagS, 1);
        if (pos < CAPS) g_flagS[pos] = i;
    }
}

// ---------------- K_fixS1 (launch #4 — ncu-captured) ------------------------
// exact h for flagged pairs: one thread per (pair, t); vectorized loads,
// strict ascending-j fp32 chain (zero-skip is bit-exact).
__global__ __launch_bounds__(256) void k_fixS1(const float* __restrict__ W_in) {
    int idx = blockIdx.x * blockDim.x + threadIdx.x;
    int n = g_nflagS; if (n > CAPS) n = CAPS;
    int pr = idx / NT, t = idx - pr * NT;
    if (pr >= n) return;
    int i = g_flagS[pr];
    int b = i >> 11, h = i & (NHID - 1);
    const uint16_t* mrow = g_jmask + (size_t)b * NIN;
    const float* wrow = W_in + (size_t)h * NIN;
    float acc = 0.0f;
    for (int j = 0; j < NIN; j += 4) {
        float4 w = *(const float4*)(wrow + j);
        uint64_t mk = *(const uint64_t*)(mrow + j);
        if ((mk >> t) & 1u)        acc = __fadd_rn(acc, w.x);
        if ((mk >> (16 + t)) & 1u) acc = __fadd_rn(acc, w.y);
        if ((mk >> (32 + t)) & 1u) acc = __fadd_rn(acc, w.z);
        if ((mk >> (48 + t)) & 1u) acc = __fadd_rn(acc, w.w);
    }
    g_fixH[pr * NT + t] = acc;
}

// exact v-chain + spike rewrite for flagged pairs (launch #5)
__global__ __launch_bounds__(256) void k_fixS2() {
    int idx = blockIdx.x * blockDim.x + threadIdx.x;
    int n = g_nflagS; if (n > CAPS) n = CAPS;
    if (idx >= n) return;
    int i = g_flagS[idx];
    int b = i >> 11, h = i & (NHID - 1);
    float v = 0.0f;
    uint32_t m = 0;
#pragma unroll
    for (int t = 0; t < NT; t++) {
        v = __fadd_rn(__fmul_rn(v, 0.3f), g_fixH[idx * NT + t]);
        if (v >= 1.0f) { m |= (1u << t); v = 0.0f; }
    }
    g_smask[i] = (uint16_t)m;
    const __half one = __float2half(1.0f);
    const __half zero = __float2half(0.0f);
#pragma unroll
    for (int t = 0; t < NT; t++)
        g_S[(size_t)(t * NB + b) * NHID + h] = ((m >> t) & 1u) ? one : zero;
}

// ---------------- output flag + exact fix + count ---------------------------
__global__ __launch_bounds__(256) void k_flagO(const float* __restrict__ b_out) {
    int i = blockIdx.x * blockDim.x + threadIdx.x;
    if (i >= NM * NOUT) return;
    float val = __fadd_rn(g_O[i], b_out[i & (NOUT - 1)]);
    if (fabsf(val) < MARGIN_O) {
        int pos = atomicAdd(&g_nflagO, 1);
        if (pos < CAPO) g_flagO[pos] = i;
    }
}

__global__ __launch_bounds__(256) void k_fixO(const float* __restrict__ W_out) {
    int idx = blockIdx.x * blockDim.x + threadIdx.x;
    int n = g_nflagO; if (n > CAPO) n = CAPO;
    if (idx >= n) return;
    int i = g_flagO[idx];
    int m = i / NOUT, o = i - m * NOUT;
    int b = m & (NB - 1), t = m / NB;
    const uint16_t* srow = g_smask + (size_t)b * NHID;
    const float* wrow = W_out + (size_t)o * NHID;
    float acc = 0.0f;
    for (int h = 0; h < NHID; h++) {
        float w = wrow[h];
        acc = __fadd_rn(acc, ((srow[h] >> t) & 1u) ? w : 0.0f);
    }
    g_O[i] = acc;
}

__global__ __launch_bounds__(256) void k_count(const float* __restrict__ b_out,
                                               float* __restrict__ out) {
    int i = blockIdx.x * blockDim.x + threadIdx.x;
    if (i >= NB * NOUT) return;
    float bo = b_out[i & (NOUT - 1)];
    float s = 0.0f;
#pragma unroll
    for (int t = 0; t < NT; t++) {
        float val = __fadd_rn(g_O[(size_t)t * (NB * NOUT) + i], bo);
        s += (val > 0.0f) ? 1.0f : 0.0f;
    }
    out[i] = s;
}

// ---------------- launch ----------------------------------------------------
extern "C" void kernel_launch(void* const* d_in, const int* in_sizes, int n_in,
                              void* d_out, int out_size) {
    const float* x     = (const float*)d_in[0];
    const float* W_in  = (const float*)d_in[1];
    const float* W_out = (const float*)d_in[2];
    const float* b_out = (const float*)d_in[3];
    float* out = (float*)d_out;

    static bool attr_set = false;
    if (!attr_set) {
        cudaFuncSetAttribute(gemm_mma, cudaFuncAttributeMaxDynamicSharedMemorySize,
                             SMEM_BYTES);
        attr_set = true;
    }

    void *p_Pre, *p_S, *p_WiH, *p_WoH, *p_H, *p_O;
    cudaGetSymbolAddress(&p_Pre, g_Pre);
    cudaGetSymbolAddress(&p_S,   g_S);
    cudaGetSymbolAddress(&p_WiH, g_WinH);
    cudaGetSymbolAddress(&p_WoH, g_WoutH);
    cudaGetSymbolAddress(&p_H,   g_H);
    cudaGetSymbolAddress(&p_O,   g_O);

    k_prep<<<PREP_W_BLOCKS + PREP_G_BLOCKS, 256>>>(x, W_in, W_out);  // #1

    {   // #2: H = PRE @ W_in^T
        dim3 grid(NHID / 128, NM / 128);
        gemm_mma<<<grid, 256, SMEM_BYTES>>>((const __half*)p_Pre,
            (const __half*)p_WiH, (float*)p_H, NM, NHID, NIN);
    }

    k_lif<<<(NB * NHID + 255) / 256, 256>>>();                       // #3
    k_fixS1<<<(CAPS * NT + 255) / 256, 256>>>(W_in);                 // #4 (ncu)
    k_fixS2<<<(CAPS + 255) / 256, 256>>>();                          // #5

    {   // #6: O = S @ W_out^T
        dim3 grid(NOUT / 128, NM / 128);
        gemm_mma<<<grid, 256, SMEM_BYTES>>>((const __half*)p_S,
            (const __half*)p_WoH, (float*)p_O, NM, NOUT, NHID);
    }

    k_flagO<<<(NM * NOUT + 255) / 256, 256>>>(b_out);                // #7
    k_fixO<<<(CAPO + 255) / 256, 256>>>(W_out);                      // #8
    k_count<<<(NB * NOUT + 255) / 256, 256>>>(b_out, out);           // #9
}

// round 14
// speedup vs baseline: 1.9907x; 1.6324x over previous
#include <cuda_runtime.h>
#include <cuda_fp16.h>
#include <cstdint>

// ============================================================================
// SpikingNetwork, T=10. B=512, input=3072, hidden=2048, out=512
// R14 = R13 with MLP-batched fix kernels: fixS1/fixO were per-thread
// latency-bound (ncu R13: fixS1 227us, occ 33%, issue 28%, ~1 load in
// flight). 8x load batching (MLP 16) hides L2/DRAM latency; FADD order
// unchanged -> bit-identical numerics.
// ============================================================================

#define NB   512
#define NIN  3072
#define NHID 2048
#define NOUT 512
#define NT   10
#define NM   (NT * NB)     // 5120

#define MARGIN_V 2.0e-3f
#define MARGIN_O 1.5e-3f
#define CAPS 131072
#define CAPO 131072

__device__ __align__(16) __half g_Pre [NM * NIN];
__device__ __align__(16) __half g_S   [NM * NHID];
__device__ __align__(16) __half g_WinH [NHID * NIN];
__device__ __align__(16) __half g_WoutH[NOUT * NHID];
__device__ float    g_H[NM * NHID];
__device__ float    g_O[NM * NOUT];
__device__ __align__(8) uint16_t g_jmask[NB * NIN];
__device__ __align__(8) uint16_t g_smask[NB * NHID];
__device__ int      g_nflagS;
__device__ int      g_flagS[CAPS];
__device__ float    g_fixH[CAPS * NT];
__device__ int      g_nflagO;
__device__ int      g_flagO[CAPO];

// ---------------- threefry2x32 (JAX-exact, 20 rounds) -----------------------
__device__ __forceinline__ uint32_t rotl32(uint32_t x, int r) {
    return __funnelshift_l(x, x, r);
}
__device__ __forceinline__ void threefry2x32(uint32_t k0, uint32_t k1,
                                             uint32_t x0, uint32_t x1,
                                             uint32_t& o0, uint32_t& o1) {
    uint32_t ks2 = k0 ^ k1 ^ 0x1BD11BDAu;
    x0 += k0; x1 += k1;
#define TF_R(r) { x0 += x1; x1 = rotl32(x1, (r)); x1 ^= x0; }
    TF_R(13) TF_R(15) TF_R(26) TF_R(6)
    x0 += k1;  x1 += ks2 + 1u;
    TF_R(17) TF_R(29) TF_R(16) TF_R(24)
    x0 += ks2; x1 += k0 + 2u;
    TF_R(13) TF_R(15) TF_R(26) TF_R(6)
    x0 += k0;  x1 += k1 + 3u;
    TF_R(17) TF_R(29) TF_R(16) TF_R(24)
    x0 += k1;  x1 += ks2 + 4u;
    TF_R(13) TF_R(15) TF_R(26) TF_R(6)
    x0 += ks2; x1 += k0 + 5u;
#undef TF_R
    o0 = x0; o1 = x1;
}

// ---------------- XLA logistic ----------------------------------------------
__device__ __forceinline__ float xla_tanh_f32(float x) {
    const float kClamp = 7.90531110763549805f;
    float ax = fabsf(x);
    float xc = fminf(fmaxf(x, -kClamp), kClamp);
    float x2 = __fmul_rn(xc, xc);
    float p;
    p = __fadd_rn(__fmul_rn(x2, -2.76076847742355e-16f), 2.00018790482477e-13f);
    p = __fadd_rn(__fmul_rn(x2, p), -8.60467152213735e-11f);
    p = __fadd_rn(__fmul_rn(x2, p),  5.12229709037114e-08f);
    p = __fadd_rn(__fmul_rn(x2, p),  1.48572235717979e-05f);
    p = __fadd_rn(__fmul_rn(x2, p),  6.37261928875436e-04f);
    p = __fadd_rn(__fmul_rn(x2, p),  4.89352455891786e-03f);
    p = __fmul_rn(xc, p);
    float q;
    q = __fadd_rn(__fmul_rn(x2, 1.19825839466702e-06f), 1.18534705686654e-04f);
    q = __fadd_rn(__fmul_rn(x2, q), 2.26843463243900e-03f);
    q = __fadd_rn(__fmul_rn(x2, q), 4.89352518554385e-03f);
    float t = __fdiv_rn(p, q);
    return (ax < 0.0004f) ? x : t;
}
__device__ __forceinline__ float xla_sigmoid_f32(float x) {
    float t = xla_tanh_f32(__fmul_rn(x, 0.5f));
    return __fadd_rn(0.5f, __fmul_rn(0.5f, t));
}

// ---------------- cp.async / ldmatrix ---------------------------------------
__device__ __forceinline__ void cp16(void* dst_smem, const void* src) {
    uint32_t d = (uint32_t)__cvta_generic_to_shared(dst_smem);
    asm volatile("cp.async.cg.shared.global [%0], [%1], 16;\n" :: "r"(d), "l"(src));
}
__device__ __forceinline__ void cp_commit() { asm volatile("cp.async.commit_group;\n"); }
__device__ __forceinline__ void cp_wait1()  { asm volatile("cp.async.wait_group 1;\n"); }
__device__ __forceinline__ void cp_wait0()  { asm volatile("cp.async.wait_group 0;\n"); }

__device__ __forceinline__ void ldsm_x4(uint32_t& r0, uint32_t& r1,
                                        uint32_t& r2, uint32_t& r3, uint32_t addr) {
    asm volatile("ldmatrix.sync.aligned.m8n8.x4.shared.b16 {%0,%1,%2,%3}, [%4];"
                 : "=r"(r0), "=r"(r1), "=r"(r2), "=r"(r3) : "r"(addr));
}

// ---------------- fp16 mma m16n8k16 -----------------------------------------
__device__ __forceinline__ void mma16816(float& d0, float& d1, float& d2, float& d3,
                                         uint32_t a0, uint32_t a1, uint32_t a2, uint32_t a3,
                                         uint32_t b0, uint32_t b1) {
    asm volatile(
        "mma.sync.aligned.m16n8k16.row.col.f32.f16.f16.f32 "
        "{%0,%1,%2,%3},{%4,%5,%6,%7},{%8,%9},{%0,%1,%2,%3};"
        : "+f"(d0), "+f"(d1), "+f"(d2), "+f"(d3)
        : "r"(a0), "r"(a1), "r"(a2), "r"(a3), "r"(b0), "r"(b1));
}

// ---------------- K_prep (launch #1): setup + weight casts + spike gen ------
#define PREP_W_ELN   (NHID * NIN + NOUT * NHID)       // 7340032
#define PREP_W_BLOCKS (PREP_W_ELN / 256)              // 28672
#define PREP_G_BLOCKS ((NB * NIN) / 256)              // 6144

__global__ __launch_bounds__(256) void k_prep(const float* __restrict__ x,
                                              const float* __restrict__ Wi,
                                              const float* __restrict__ Wo) {
    const int blk = blockIdx.x;
    if (blk < PREP_W_BLOCKS) {
        if (blk == 0 && threadIdx.x == 0) { g_nflagS = 0; g_nflagO = 0; }
        int i = blk * 256 + threadIdx.x;
        const int n1 = NHID * NIN;
        if (i < n1) g_WinH[i] = __float2half_rn(Wi[i]);
        else        g_WoutH[i - n1] = __float2half_rn(Wo[i - n1]);
        return;
    }
    __shared__ uint32_t sk0[NT], sk1[NT];
    if (threadIdx.x < NT) {
        uint32_t a, b;
        threefry2x32(0u, 42u, 0u, (uint32_t)threadIdx.x, a, b);
        sk0[threadIdx.x] = a; sk1[threadIdx.x] = b;
    }
    __syncthreads();
    int idx = (blk - PREP_W_BLOCKS) * 256 + threadIdx.x;
    int b = idx / NIN, j = idx - b * NIN;
    float p = xla_sigmoid_f32(x[idx]);
    uint32_t m = 0;
#pragma unroll
    for (int t = 0; t < NT; t++) {
        uint32_t a, bb;
        threefry2x32(sk0[t], sk1[t], 0u, (uint32_t)idx, a, bb);
        uint32_t bits = a ^ bb;
        float u = __uint_as_float((bits >> 9) | 0x3F800000u) - 1.0f;
        m |= (u < p) ? (1u << t) : 0u;
    }
    g_jmask[idx] = (uint16_t)m;
    const __half one = __float2half(1.0f);
    const __half zero = __float2half(0.0f);
#pragma unroll
    for (int t = 0; t < NT; t++)
        g_Pre[(size_t)(t * NB + b) * NIN + j] = ((m >> t) & 1u) ? one : zero;
}

// ---------------- fp16 tensor-core GEMM (launch #2) -------------------------
#define GTK 64
#define ROWH 72
#define NSTG 2
#define TILE_ELN (128 * ROWH)
#define STAGE_ELN (2 * TILE_ELN)
#define SMEM_BYTES (NSTG * STAGE_ELN * 2)   // 73728

__global__ __launch_bounds__(256)
void gemm_mma(const __half* __restrict__ A,
              const __half* __restrict__ B,
              float* __restrict__ C, int M, int N, int K) {
    extern __shared__ __half smem[];

    const int tid  = threadIdx.x;
    const int m0   = blockIdx.y * 128;
    const int n0   = blockIdx.x * 128;
    const int warp = tid >> 5;
    const int lane = tid & 31;
    const int wm   = (warp & 1) * 64;
    const int wn   = (warp >> 1) * 32;
    const int r    = lane >> 2;
    const int c2   = (lane & 3) * 2;

    const uint32_t sbase = (uint32_t)__cvta_generic_to_shared(smem);
    const uint32_t aLane = (uint32_t)(((wm + (lane & 15)) * ROWH + ((lane >> 4) * 8)) * 2);
    const uint32_t bLane = (uint32_t)(((wn + 8 * (lane >> 4) + (lane & 7)) * ROWH
                                       + (((lane >> 3) & 1) * 8)) * 2);

    float acc[4][4][4];
#pragma unroll
    for (int mi = 0; mi < 4; mi++)
#pragma unroll
        for (int nj = 0; nj < 4; nj++)
#pragma unroll
            for (int q = 0; q < 4; q++) acc[mi][nj][q] = 0.0f;

    auto issue_slab = [&](int kb, int s) {
        __half* st = smem + s * STAGE_ELN;
#pragma unroll
        for (int it = 0; it < 4; it++) {
            int idx = it * 256 + tid;
            int row = idx >> 3;
            int ch  = idx & 7;
            size_t go = (size_t)row * K + kb + ch * 8;
            int so = row * ROWH + ch * 8;
            cp16(st + so,            A + (size_t)m0 * K + go);
            cp16(st + TILE_ELN + so, B + (size_t)n0 * K + go);
        }
        cp_commit();
    };

    const int nslab = K / GTK;
    issue_slab(0, 0);
    int s = 0;
    for (int sl = 0; sl < nslab; sl++) {
        if (sl + 1 < nslab) { issue_slab((sl + 1) * GTK, s ^ 1); cp_wait1(); }
        else                { cp_wait0(); }
        __syncthreads();

        const uint32_t stA = sbase + (uint32_t)(s * STAGE_ELN) * 2;
        const uint32_t stB = stA + TILE_ELN * 2;

#pragma unroll
        for (int kc = 0; kc < 4; kc++) {
            const uint32_t kh2 = (uint32_t)(kc * 16 * 2);
            uint32_t af[4][4];
#pragma unroll
            for (int mi = 0; mi < 4; mi++)
                ldsm_x4(af[mi][0], af[mi][1], af[mi][2], af[mi][3],
                        stA + aLane + (uint32_t)(16 * mi * ROWH * 2) + kh2);

            uint32_t bf[4][2];
#pragma unroll
            for (int p = 0; p < 2; p++) {
                uint32_t r0, r1, r2, r3;
                ldsm_x4(r0, r1, r2, r3,
                        stB + bLane + (uint32_t)(16 * p * ROWH * 2) + kh2);
                bf[2 * p][0] = r0; bf[2 * p][1] = r1;
                bf[2 * p + 1][0] = r2; bf[2 * p + 1][1] = r3;
            }
#pragma unroll
            for (int mi = 0; mi < 4; mi++)
#pragma unroll
                for (int nj = 0; nj < 4; nj++)
                    mma16816(acc[mi][nj][0], acc[mi][nj][1], acc[mi][nj][2], acc[mi][nj][3],
                             af[mi][0], af[mi][1], af[mi][2], af[mi][3],
                             bf[nj][0], bf[nj][1]);
        }
        __syncthreads();
        s ^= 1;
    }

#pragma unroll
    for (int mi = 0; mi < 4; mi++)
#pragma unroll
        for (int nj = 0; nj < 4; nj++) {
            int row = m0 + wm + 16 * mi + r;
            int col = n0 + wn + 8 * nj + c2;
            *(float2*)&C[(size_t)row * N + col] =
                make_float2(acc[mi][nj][0], acc[mi][nj][1]);
            *(float2*)&C[(size_t)(row + 8) * N + col] =
                make_float2(acc[mi][nj][2], acc[mi][nj][3]);
        }
}

// ---------------- K_lif (launch #3): LIF scan + flagging --------------------
__global__ __launch_bounds__(256) void k_lif() {
    int i = blockIdx.x * blockDim.x + threadIdx.x;
    if (i >= NB * NHID) return;
    int b = i >> 11, h = i & (NHID - 1);
    float v = 0.0f;
    uint32_t m = 0;
    bool flag = false;
#pragma unroll
    for (int t = 0; t < NT; t++) {
        float hv = g_H[(size_t)(t * NB + b) * NHID + h];
        v = __fadd_rn(__fmul_rn(v, 0.3f), hv);
        flag |= fabsf(v - 1.0f) < MARGIN_V;
        if (v >= 1.0f) { m |= (1u << t); v = 0.0f; }
    }
    g_smask[i] = (uint16_t)m;
    const __half one = __float2half(1.0f);
    const __half zero = __float2half(0.0f);
#pragma unroll
    for (int t = 0; t < NT; t++)
        g_S[(size_t)(t * NB + b) * NHID + h] = ((m >> t) & 1u) ? one : zero;
    if (flag) {
        int pos = atomicAdd(&g_nflagS, 1);
        if (pos < CAPS) g_flagS[pos] = i;
    }
}

// ---------------- K_fixS1 (launch #4 — ncu-captured) ------------------------
// exact h for flagged pairs: one thread per (pair, t). 8x batched loads
// (MLP 16) then predicated FADDs in strict ascending-j order (bit-exact).
__global__ __launch_bounds__(256) void k_fixS1(const float* __restrict__ W_in) {
    int idx = blockIdx.x * blockDim.x + threadIdx.x;
    int n = g_nflagS; if (n > CAPS) n = CAPS;
    int pr = idx / NT, t = idx - pr * NT;
    if (pr >= n) return;
    int i = g_flagS[pr];
    int b = i >> 11, h = i & (NHID - 1);
    const uint16_t* mrow = g_jmask + (size_t)b * NIN;
    const float* wrow = W_in + (size_t)h * NIN;
    float acc = 0.0f;
    for (int j = 0; j < NIN; j += 32) {
        float4   w[8];
        uint64_t mk[8];
#pragma unroll
        for (int u = 0; u < 8; u++) {
            w[u]  = *(const float4*)(wrow + j + u * 4);
            mk[u] = *(const uint64_t*)(mrow + j + u * 4);
        }
#pragma unroll
        for (int u = 0; u < 8; u++) {
            if ((mk[u] >> t) & 1u)        acc = __fadd_rn(acc, w[u].x);
            if ((mk[u] >> (16 + t)) & 1u) acc = __fadd_rn(acc, w[u].y);
            if ((mk[u] >> (32 + t)) & 1u) acc = __fadd_rn(acc, w[u].z);
            if ((mk[u] >> (48 + t)) & 1u) acc = __fadd_rn(acc, w[u].w);
        }
    }
    g_fixH[pr * NT + t] = acc;
}

// exact v-chain + spike rewrite for flagged pairs (launch #5)
__global__ __launch_bounds__(256) void k_fixS2() {
    int idx = blockIdx.x * blockDim.x + threadIdx.x;
    int n = g_nflagS; if (n > CAPS) n = CAPS;
    if (idx >= n) return;
    int i = g_flagS[idx];
    int b = i >> 11, h = i & (NHID - 1);
    float v = 0.0f;
    uint32_t m = 0;
#pragma unroll
    for (int t = 0; t < NT; t++) {
        v = __fadd_rn(__fmul_rn(v, 0.3f), g_fixH[idx * NT + t]);
        if (v >= 1.0f) { m |= (1u << t); v = 0.0f; }
    }
    g_smask[i] = (uint16_t)m;
    const __half one = __float2half(1.0f);
    const __half zero = __float2half(0.0f);
#pragma unroll
    for (int t = 0; t < NT; t++)
        g_S[(size_t)(t * NB + b) * NHID + h] = ((m >> t) & 1u) ? one : zero;
}

// ---------------- output flag + exact fix + count ---------------------------
__global__ __launch_bounds__(256) void k_flagO(const float* __restrict__ b_out) {
    int i = blockIdx.x * blockDim.x + threadIdx.x;
    if (i >= NM * NOUT) return;
    float val = __fadd_rn(g_O[i], b_out[i & (NOUT - 1)]);
    if (fabsf(val) < MARGIN_O) {
        int pos = atomicAdd(&g_nflagO, 1);
        if (pos < CAPO) g_flagO[pos] = i;
    }
}

// exact O for flagged (t,b,o): 8x batched loads (MLP 16), ascending-h order.
__global__ __launch_bounds__(256) void k_fixO(const float* __restrict__ W_out) {
    int idx = blockIdx.x * blockDim.x + threadIdx.x;
    int n = g_nflagO; if (n > CAPO) n = CAPO;
    if (idx >= n) return;
    int i = g_flagO[idx];
    int m = i / NOUT, o = i - m * NOUT;
    int b = m & (NB - 1), t = m / NB;
    const uint16_t* srow = g_smask + (size_t)b * NHID;
    const float* wrow = W_out + (size_t)o * NHID;
    float acc = 0.0f;
    for (int h = 0; h < NHID; h += 32) {
        float4   w[8];
        uint64_t mk[8];
#pragma unroll
        for (int u = 0; u < 8; u++) {
            w[u]  = *(const float4*)(wrow + h + u * 4);
            mk[u] = *(const uint64_t*)(srow + h + u * 4);
        }
#pragma unroll
        for (int u = 0; u < 8; u++) {
            if ((mk[u] >> t) & 1u)        acc = __fadd_rn(acc, w[u].x);
            if ((mk[u] >> (16 + t)) & 1u) acc = __fadd_rn(acc, w[u].y);
            if ((mk[u] >> (32 + t)) & 1u) acc = __fadd_rn(acc, w[u].z);
            if ((mk[u] >> (48 + t)) & 1u) acc = __fadd_rn(acc, w[u].w);
        }
    }
    g_O[i] = acc;
}

__global__ __launch_bounds__(256) void k_count(const float* __restrict__ b_out,
                                               float* __restrict__ out) {
    int i = blockIdx.x * blockDim.x + threadIdx.x;
    if (i >= NB * NOUT) return;
    float bo = b_out[i & (NOUT - 1)];
    float s = 0.0f;
#pragma unroll
    for (int t = 0; t < NT; t++) {
        float val = __fadd_rn(g_O[(size_t)t * (NB * NOUT) + i], bo);
        s += (val > 0.0f) ? 1.0f : 0.0f;
    }
    out[i] = s;
}

// ---------------- launch ----------------------------------------------------
extern "C" void kernel_launch(void* const* d_in, const int* in_sizes, int n_in,
                              void* d_out, int out_size) {
    const float* x     = (const float*)d_in[0];
    const float* W_in  = (const float*)d_in[1];
    const float* W_out = (const float*)d_in[2];
    const float* b_out = (const float*)d_in[3];
    float* out = (float*)d_out;

    static bool attr_set = false;
    if (!attr_set) {
        cudaFuncSetAttribute(gemm_mma, cudaFuncAttributeMaxDynamicSharedMemorySize,
                             SMEM_BYTES);
        attr_set = true;
    }

    void *p_Pre, *p_S, *p_WiH, *p_WoH, *p_H, *p_O;
    cudaGetSymbolAddress(&p_Pre, g_Pre);
    cudaGetSymbolAddress(&p_S,   g_S);
    cudaGetSymbolAddress(&p_WiH, g_WinH);
    cudaGetSymbolAddress(&p_WoH, g_WoutH);
    cudaGetSymbolAddress(&p_H,   g_H);
    cudaGetSymbolAddress(&p_O,   g_O);

    k_prep<<<PREP_W_BLOCKS + PREP_G_BLOCKS, 256>>>(x, W_in, W_out);  // #1

    {   // #2: H = PRE @ W_in^T
        dim3 grid(NHID / 128, NM / 128);
        gemm_mma<<<grid, 256, SMEM_BYTES>>>((const __half*)p_Pre,
            (const __half*)p_WiH, (float*)p_H, NM, NHID, NIN);
    }

    k_lif<<<(NB * NHID + 255) / 256, 256>>>();                       // #3
    k_fixS1<<<(CAPS * NT + 255) / 256, 256>>>(W_in);                 // #4 (ncu)
    k_fixS2<<<(CAPS + 255) / 256, 256>>>();                          // #5

    {   // #6: O = S @ W_out^T
        dim3 grid(NOUT / 128, NM / 128);
        gemm_mma<<<grid, 256, SMEM_BYTES>>>((const __half*)p_S,
            (const __half*)p_WoH, (float*)p_O, NM, NOUT, NHID);
    }

    k_flagO<<<(NM * NOUT + 255) / 256, 256>>>(b_out);                // #7
    k_fixO<<<(CAPO + 255) / 256, 256>>>(W_out);                      // #8
    k_count<<<(NB * NOUT + 255) / 256, 256>>>(b_out, out);           // #9
}